// round 3
// baseline (speedup 1.0000x reference)
#include <cuda_runtime.h>
#include <cuda_fp16.h>
#include <cstdint>

#define B_DIM 1024
#define K_DIM 512
#define H_DIM 512
#define J_DIM 256
#define D_DIM 4

#define SCALE_F 512.0f
#define INV_SCALE (1.0f/512.0f)

// scratch (static device globals: allocation-free)
__device__ __half g_xh[B_DIM * K_DIM];
__device__ __half g_w0h[(size_t)J_DIM * H_DIM * K_DIM];

__device__ __forceinline__ uint32_t smem_u32(const void* p) {
    uint32_t a;
    asm("{ .reg .u64 t; cvta.to.shared.u64 t, %1; cvt.u32.u64 %0, t; }" : "=r"(a) : "l"(p));
    return a;
}

#define CP_ASYNC16(dst, src) \
    asm volatile("cp.async.cg.shared.global [%0], [%1], 16;" \
        :: "r"((uint32_t)(dst)), "l"(src) : "memory")
#define CP_COMMIT() asm volatile("cp.async.commit_group;" ::: "memory")
#define CP_WAIT(n)  asm volatile("cp.async.wait_group %0;" :: "n"(n) : "memory")

#define LDSM_X4(r0,r1,r2,r3,addr) \
    asm volatile("ldmatrix.sync.aligned.m8n8.x4.shared.b16 {%0,%1,%2,%3}, [%4];" \
        : "=r"(r0), "=r"(r1), "=r"(r2), "=r"(r3) : "r"(addr))

#define MMA16816(d, a, b0, b1) \
    asm volatile("mma.sync.aligned.m16n8k16.row.col.f32.f16.f16.f32 " \
        "{%0,%1,%2,%3}, {%4,%5,%6,%7}, {%8,%9}, {%0,%1,%2,%3};" \
        : "+f"((d)[0]), "+f"((d)[1]), "+f"((d)[2]), "+f"((d)[3]) \
        : "r"((a)[0]), "r"((a)[1]), "r"((a)[2]), "r"((a)[3]), "r"(b0), "r"(b1))

// ---------------- prep kernels ----------------
__global__ void prep_x_kernel(const float* __restrict__ x, const float* __restrict__ logvar,
                              float* __restrict__ out, int out_size) {
    int t = blockIdx.x * blockDim.x + threadIdx.x;
    if (t < (B_DIM * K_DIM) / 4) {
        float4 v = reinterpret_cast<const float4*>(x)[t];
        __half2 h0 = __floats2half2_rn(v.x, v.y);
        __half2 h1 = __floats2half2_rn(v.z, v.w);
        uint2 pk;
        pk.x = *reinterpret_cast<uint32_t*>(&h0);
        pk.y = *reinterpret_cast<uint32_t*>(&h1);
        reinterpret_cast<uint2*>(g_xh)[t] = pk;
    }
    if (blockIdx.x == 0) {
        int extra = out_size - B_DIM * J_DIM;
        if ((int)threadIdx.x < extra && threadIdx.x < D_DIM)
            out[B_DIM * J_DIM + threadIdx.x] = logvar[threadIdx.x];
    }
}

// W0eff[j,h,k] = W0[j,h,k] * w[i,j,k] * 512  -> fp16
__global__ void prep_w0_kernel(const float* __restrict__ W0, const float* __restrict__ w,
                               const int* __restrict__ ip) {
    size_t t = (size_t)blockIdx.x * blockDim.x + threadIdx.x;
    size_t e = t * 4;
    int j = (int)(e >> 18);          // H*K = 2^18
    int k = (int)(e & (K_DIM - 1));
    float4 a = *reinterpret_cast<const float4*>(W0 + e);
    const float* wip = w + (size_t)ip[0] * J_DIM * K_DIM + (size_t)j * K_DIM + k;
    float4 b = *reinterpret_cast<const float4*>(wip);
    __half2 h0 = __floats2half2_rn(a.x * b.x * SCALE_F, a.y * b.y * SCALE_F);
    __half2 h1 = __floats2half2_rn(a.z * b.z * SCALE_F, a.w * b.w * SCALE_F);
    uint2 pk;
    pk.x = *reinterpret_cast<uint32_t*>(&h0);
    pk.y = *reinterpret_cast<uint32_t*>(&h1);
    *reinterpret_cast<uint2*>(g_w0h + e) = pk;
}

// ---------------- fused grouped-GEMM + epilogue (HMMA) ----------------
// CTA = (j, m_tile). X tile [128 x 512] fp16 resident in smem.
// W0eff[j] processed in 4 h-chunks of 128, each staged in k-chunks of 64
// (double buffered). Warp tile 64x32, 8 warps (2 M x 4 N) cover 128x128.
// Epilogue per h-chunk: mu partial = sum_h leaky(acc/512 + b0)*W1 -> smem sums.
__global__ void __launch_bounds__(256, 1)
encoder_gemm(const float* __restrict__ b0g, const float* __restrict__ W1g,
             const float* __restrict__ b1g, float* __restrict__ out) {
    extern __shared__ char smem[];
    const uint32_t S_X = smem_u32(smem);            // 131072 B
    const uint32_t S_W = S_X + 131072;              // 2 x 16384 B
    float2* bw   = reinterpret_cast<float2*>(smem + 163840);  // 512 float2
    float*  sums = reinterpret_cast<float*>(smem + 167936);   // 128 floats

    const int tid  = threadIdx.x;
    const int wid  = tid >> 5;
    const int lane = tid & 31;
    const int wm = wid & 1;          // M block (64 rows)
    const int wn = wid >> 1;         // N block (32 cols within 128 h-chunk)
    const int j  = blockIdx.x >> 3;
    const int mt8 = blockIdx.x & 7;

    const __half* Ab = g_xh + (size_t)(mt8 * 128) * K_DIM;
    const __half* Bb = g_w0h + (size_t)j * H_DIM * K_DIM;

    // b0 / W1 into smem
    for (int c = tid; c < H_DIM; c += 256)
        bw[c] = make_float2(b0g[j * H_DIM + c], W1g[j * H_DIM + c]);
    if (tid < 128) sums[tid] = 0.f;

    // X tile load: 8192 16B chunks, xor-swizzled (64 chunks per 1024B row)
#pragma unroll
    for (int it = 0; it < 32; ++it) {
        int c = tid + it * 256;
        int row = c >> 6, kb = c & 63;
        int swz = (kb & 56) | ((kb ^ row) & 7);
        CP_ASYNC16(S_X + row * 1024 + swz * 16, Ab + (size_t)row * K_DIM + kb * 8);
    }

    // W chunk stage: cc in [0,32): hc = cc>>3, kc = cc&7. 128 rows x 128B.
    auto stage_w = [&](int cc, int buf) {
        const __half* src = Bb + (size_t)((cc >> 3) * 128) * K_DIM + (cc & 7) * 64;
        uint32_t dstb = S_W + buf * 16384;
#pragma unroll
        for (int it = 0; it < 4; ++it) {
            int c = tid + it * 256;
            int row = c >> 3, kb = c & 7;
            CP_ASYNC16(dstb + row * 128 + (kb ^ (row & 7)) * 16,
                       src + (size_t)row * K_DIM + kb * 8);
        }
    };

    stage_w(0, 0);
    CP_COMMIT();   // group 0 = X tile + W chunk 0

    float acc[4][4][4];
#pragma unroll
    for (int mt = 0; mt < 4; ++mt)
#pragma unroll
        for (int nt = 0; nt < 4; ++nt)
#pragma unroll
            for (int q = 0; q < 4; ++q) acc[mt][nt][q] = 0.f;

    // ldmatrix lane-address components (constant per thread)
    const int a_row = wm * 64 + (lane & 15);          // + mt*16
    const int a_ck  = lane >> 4;                      // k-half select
    const int b_row = wn * 32 + (lane & 7) + ((lane >> 4) << 3);  // + np*16
    const int b_kb  = (lane >> 3) & 1;                // k-half select

#pragma unroll 1
    for (int cc = 0; cc < 32; ++cc) {
        int buf = cc & 1;
        if (cc < 31) { stage_w(cc + 1, buf ^ 1); CP_COMMIT(); }
        if (cc < 31) { CP_WAIT(1); } else { CP_WAIT(0); }
        __syncthreads();

        uint32_t wbase = S_W + buf * 16384;
        int kc = cc & 7;
#pragma unroll
        for (int kk = 0; kk < 4; ++kk) {
            uint32_t afr[4][4], bfr[2][4];
#pragma unroll
            for (int mt = 0; mt < 4; ++mt) {
                int r = a_row + mt * 16;
                int cidx = kc * 8 + kk * 2 + a_ck;
                int swz = (cidx & 56) | ((cidx ^ r) & 7);
                LDSM_X4(afr[mt][0], afr[mt][1], afr[mt][2], afr[mt][3],
                        S_X + r * 1024 + swz * 16);
            }
#pragma unroll
            for (int np = 0; np < 2; ++np) {
                int hl = b_row + np * 16;
                int kb = kk * 2 + b_kb;
                LDSM_X4(bfr[np][0], bfr[np][1], bfr[np][2], bfr[np][3],
                        wbase + hl * 128 + (kb ^ (hl & 7)) * 16);
            }
#pragma unroll
            for (int mt = 0; mt < 4; ++mt)
#pragma unroll
                for (int nt = 0; nt < 4; ++nt)
                    MMA16816(acc[mt][nt], afr[mt],
                             bfr[nt >> 1][(nt & 1) * 2], bfr[nt >> 1][(nt & 1) * 2 + 1]);
        }
        __syncthreads();

        if (kc == 7) {
            // epilogue for h-chunk hc = cc>>3
            int hc = cc >> 3;
#pragma unroll
            for (int mt = 0; mt < 4; ++mt) {
                float sA = 0.f, sB = 0.f;
#pragma unroll
                for (int nt = 0; nt < 4; ++nt) {
                    int h = hc * 128 + wn * 32 + nt * 8 + (lane & 3) * 2;
                    float2 bw0 = bw[h];
                    float2 bw1 = bw[h + 1];
                    float v;
                    v = fmaf(acc[mt][nt][0], INV_SCALE, bw0.x);
                    v = (v > 0.f) ? v : 0.01f * v;  sA = fmaf(v, bw0.y, sA);
                    v = fmaf(acc[mt][nt][1], INV_SCALE, bw1.x);
                    v = (v > 0.f) ? v : 0.01f * v;  sA = fmaf(v, bw1.y, sA);
                    v = fmaf(acc[mt][nt][2], INV_SCALE, bw0.x);
                    v = (v > 0.f) ? v : 0.01f * v;  sB = fmaf(v, bw0.y, sB);
                    v = fmaf(acc[mt][nt][3], INV_SCALE, bw1.x);
                    v = (v > 0.f) ? v : 0.01f * v;  sB = fmaf(v, bw1.y, sB);
#pragma unroll
                    for (int q = 0; q < 4; ++q) acc[mt][nt][q] = 0.f;
                }
                sA += __shfl_xor_sync(0xffffffffu, sA, 1);
                sA += __shfl_xor_sync(0xffffffffu, sA, 2);
                sB += __shfl_xor_sync(0xffffffffu, sB, 1);
                sB += __shfl_xor_sync(0xffffffffu, sB, 2);
                if ((lane & 3) == 0) {
                    int row = wm * 64 + mt * 16 + (lane >> 2);
                    atomicAdd(&sums[row], sA);
                    atomicAdd(&sums[row + 8], sB);
                }
            }
        }
    }

    __syncthreads();
    if (tid < 128)
        out[(size_t)(mt8 * 128 + tid) * J_DIM + j] = sums[tid] + b1g[j];
}

// ---------------- launch ----------------
extern "C" void kernel_launch(void* const* d_in, const int* in_sizes, int n_in,
                              void* d_out, int out_size) {
    const float* x      = (const float*)d_in[0];
    const int*   ip     = (const int*)d_in[1];
    const float* w      = (const float*)d_in[2];
    const float* W0     = (const float*)d_in[3];
    const float* b0     = (const float*)d_in[4];
    const float* W1     = (const float*)d_in[5];
    const float* b1     = (const float*)d_in[6];
    const float* logvar = (const float*)d_in[7];
    float* out = (float*)d_out;

    const int SMEM_BYTES = 168448;
    cudaFuncSetAttribute(encoder_gemm, cudaFuncAttributeMaxDynamicSharedMemorySize, SMEM_BYTES);

    prep_x_kernel<<<512, 256>>>(x, logvar, out, out_size);
    prep_w0_kernel<<<(J_DIM * H_DIM * K_DIM / 4) / 256, 256>>>(W0, w, ip);
    encoder_gemm<<<J_DIM * (B_DIM / 128), 256, SMEM_BYTES>>>(b0, W1, b1, out);
}

// round 4
// speedup vs baseline: 1.0858x; 1.0858x over previous
#include <cuda_runtime.h>
#include <cuda_fp16.h>
#include <cstdint>

#define B_DIM 1024
#define K_DIM 512
#define H_DIM 512
#define J_DIM 256
#define D_DIM 4

#define SCALE_F 512.0f
#define INV_SCALE (1.0f/512.0f)

// scratch (static device globals: allocation-free)
__device__ __half g_xh[B_DIM * K_DIM];
__device__ __half g_w0h[(size_t)J_DIM * H_DIM * K_DIM];

__device__ __forceinline__ uint32_t smem_u32(const void* p) {
    uint32_t a;
    asm("{ .reg .u64 t; cvta.to.shared.u64 t, %1; cvt.u32.u64 %0, t; }" : "=r"(a) : "l"(p));
    return a;
}

#define CP_ASYNC16(dst, src) \
    asm volatile("cp.async.cg.shared.global [%0], [%1], 16;" \
        :: "r"((uint32_t)(dst)), "l"(src) : "memory")
#define CP_COMMIT() asm volatile("cp.async.commit_group;" ::: "memory")
#define CP_WAIT(n)  asm volatile("cp.async.wait_group %0;" :: "n"(n) : "memory")

#define LDSM_X4(r0,r1,r2,r3,addr) \
    asm volatile("ldmatrix.sync.aligned.m8n8.x4.shared.b16 {%0,%1,%2,%3}, [%4];" \
        : "=r"(r0), "=r"(r1), "=r"(r2), "=r"(r3) : "r"(addr))

#define MMA16816(d, a, b0, b1) \
    asm volatile("mma.sync.aligned.m16n8k16.row.col.f32.f16.f16.f32 " \
        "{%0,%1,%2,%3}, {%4,%5,%6,%7}, {%8,%9}, {%0,%1,%2,%3};" \
        : "+f"((d)[0]), "+f"((d)[1]), "+f"((d)[2]), "+f"((d)[3]) \
        : "r"((a)[0]), "r"((a)[1]), "r"((a)[2]), "r"((a)[3]), "r"(b0), "r"(b1))

// ---------------- merged prep kernel ----------------
// All blocks: W0eff[j,h,k] = W0[j,h,k] * w[i,j,k] * 512 -> fp16 (4 elems/thread)
// Blocks [0,512): also convert x -> fp16. Block 0: logvar tail of output.
__global__ void prep_kernel(const float* __restrict__ W0, const float* __restrict__ w,
                            const int* __restrict__ ip,
                            const float* __restrict__ x, const float* __restrict__ logvar,
                            float* __restrict__ out, int out_size) {
    size_t t = (size_t)blockIdx.x * blockDim.x + threadIdx.x;
    size_t e = t * 4;
    int j = (int)(e >> 18);          // H*K = 2^18
    int k = (int)(e & (K_DIM - 1));
    float4 a = *reinterpret_cast<const float4*>(W0 + e);
    const float* wip = w + (size_t)ip[0] * J_DIM * K_DIM + (size_t)j * K_DIM + k;
    float4 b = *reinterpret_cast<const float4*>(wip);
    __half2 h0 = __floats2half2_rn(a.x * b.x * SCALE_F, a.y * b.y * SCALE_F);
    __half2 h1 = __floats2half2_rn(a.z * b.z * SCALE_F, a.w * b.w * SCALE_F);
    uint2 pk;
    pk.x = *reinterpret_cast<uint32_t*>(&h0);
    pk.y = *reinterpret_cast<uint32_t*>(&h1);
    *reinterpret_cast<uint2*>(g_w0h + e) = pk;

    if (t < (B_DIM * K_DIM) / 4) {
        float4 v = reinterpret_cast<const float4*>(x)[t];
        __half2 x0 = __floats2half2_rn(v.x, v.y);
        __half2 x1 = __floats2half2_rn(v.z, v.w);
        uint2 xp;
        xp.x = *reinterpret_cast<uint32_t*>(&x0);
        xp.y = *reinterpret_cast<uint32_t*>(&x1);
        reinterpret_cast<uint2*>(g_xh)[t] = xp;
    }
    if (blockIdx.x == 0) {
        int extra = out_size - B_DIM * J_DIM;
        if ((int)threadIdx.x < extra && threadIdx.x < D_DIM)
            out[B_DIM * J_DIM + threadIdx.x] = logvar[threadIdx.x];
    }
}

// ---------------- fused grouped-GEMM + epilogue (HMMA) ----------------
// CTA = (j, m_tile). X tile [128 x 512] fp16 resident in smem.
// W0eff[j]: 4 h-chunks of 128, each in 4 k-chunks of 128 (double buffered,
// 32KB/stage). Warp tile 64x32, 8 warps (2M x 4N) cover 128x128.
// One __syncthreads per iteration.
__global__ void __launch_bounds__(256, 1)
encoder_gemm(const float* __restrict__ b0g, const float* __restrict__ W1g,
             const float* __restrict__ b1g, float* __restrict__ out) {
    extern __shared__ char smem[];
    const uint32_t S_X = smem_u32(smem);            // 131072 B
    const uint32_t S_W = S_X + 131072;              // 2 x 32768 B
    float2* bw   = reinterpret_cast<float2*>(smem + 196608);  // 512 float2
    float*  sums = reinterpret_cast<float*>(smem + 200704);   // 128 floats

    const int tid  = threadIdx.x;
    const int wid  = tid >> 5;
    const int lane = tid & 31;
    const int wm = wid & 1;          // M block (64 rows)
    const int wn = wid >> 1;         // N block (32 cols within 128 h-chunk)
    const int j  = blockIdx.x >> 3;
    const int mt8 = blockIdx.x & 7;

    const __half* Ab = g_xh + (size_t)(mt8 * 128) * K_DIM;
    const __half* Bb = g_w0h + (size_t)j * H_DIM * K_DIM;

    // b0 / W1 into smem
    for (int c = tid; c < H_DIM; c += 256)
        bw[c] = make_float2(b0g[j * H_DIM + c], W1g[j * H_DIM + c]);
    if (tid < 128) sums[tid] = 0.f;

    // X tile: 8192 16B chunks, xor-swizzled (64 chunks per 1024B row)
#pragma unroll
    for (int it = 0; it < 32; ++it) {
        int c = tid + it * 256;
        int row = c >> 6, kb = c & 63;
        int swz = (kb & 56) | ((kb ^ row) & 7);
        CP_ASYNC16(S_X + row * 1024 + swz * 16, Ab + (size_t)row * K_DIM + kb * 8);
    }

    // W chunk stage: cc in [0,16): hc = cc>>2, kc = cc&3.
    // 128 rows(h) x 128k fp16 = 256B/row, 16 chunks/row.
    auto stage_w = [&](int cc, int buf) {
        const __half* src = Bb + (size_t)((cc >> 2) * 128) * K_DIM + (cc & 3) * 128;
        uint32_t dstb = S_W + buf * 32768;
#pragma unroll
        for (int it = 0; it < 8; ++it) {
            int c = tid + it * 256;
            int row = c >> 4, kb = c & 15;
            int swz = (kb & 8) | ((kb ^ row) & 7);
            CP_ASYNC16(dstb + row * 256 + swz * 16,
                       src + (size_t)row * K_DIM + kb * 8);
        }
    };

    stage_w(0, 0);
    CP_COMMIT();   // group: X tile + W chunk 0

    float acc[4][4][4];
#pragma unroll
    for (int mt = 0; mt < 4; ++mt)
#pragma unroll
        for (int nt = 0; nt < 4; ++nt)
#pragma unroll
            for (int q = 0; q < 4; ++q) acc[mt][nt][q] = 0.f;

    // ldmatrix lane-address components (constant per thread)
    const int a_row = wm * 64 + (lane & 15);          // + mt*16
    const int a_ck  = lane >> 4;                      // k-half select
    const int b_row = wn * 32 + (lane & 7) + ((lane >> 4) << 3);  // + np*16
    const int b_kb  = (lane >> 3) & 1;                // k-half select

#pragma unroll 1
    for (int cc = 0; cc < 16; ++cc) {
        int buf = cc & 1;
        CP_WAIT(0);          // stage cc (and initial X) landed for this thread
        __syncthreads();     // visible to all; all reads of buf^1 (iter cc-1) done
        if (cc < 15) { stage_w(cc + 1, buf ^ 1); CP_COMMIT(); }

        uint32_t wbase = S_W + buf * 32768;
        int kc = cc & 3;
#pragma unroll
        for (int kk = 0; kk < 8; ++kk) {
            uint32_t afr[4][4], bfr[2][4];
#pragma unroll
            for (int mt = 0; mt < 4; ++mt) {
                int r = a_row + mt * 16;
                int cidx = kc * 16 + kk * 2 + a_ck;
                int swz = (cidx & 56) | ((cidx ^ r) & 7);
                LDSM_X4(afr[mt][0], afr[mt][1], afr[mt][2], afr[mt][3],
                        S_X + r * 1024 + swz * 16);
            }
#pragma unroll
            for (int np = 0; np < 2; ++np) {
                int hl = b_row + np * 16;
                int kb = kk * 2 + b_kb;
                int swz = (kb & 8) | ((kb ^ hl) & 7);
                LDSM_X4(bfr[np][0], bfr[np][1], bfr[np][2], bfr[np][3],
                        wbase + hl * 256 + swz * 16);
            }
#pragma unroll
            for (int mt = 0; mt < 4; ++mt)
#pragma unroll
                for (int nt = 0; nt < 4; ++nt)
                    MMA16816(acc[mt][nt], afr[mt],
                             bfr[nt >> 1][(nt & 1) * 2], bfr[nt >> 1][(nt & 1) * 2 + 1]);
        }

        if (kc == 3) {
            // epilogue for h-chunk hc = cc>>2
            int hc = cc >> 2;
#pragma unroll
            for (int mt = 0; mt < 4; ++mt) {
                float sA = 0.f, sB = 0.f;
#pragma unroll
                for (int nt = 0; nt < 4; ++nt) {
                    int h = hc * 128 + wn * 32 + nt * 8 + (lane & 3) * 2;
                    float2 bw0 = bw[h];
                    float2 bw1 = bw[h + 1];
                    float v;
                    v = fmaf(acc[mt][nt][0], INV_SCALE, bw0.x);
                    v = (v > 0.f) ? v : 0.01f * v;  sA = fmaf(v, bw0.y, sA);
                    v = fmaf(acc[mt][nt][1], INV_SCALE, bw1.x);
                    v = (v > 0.f) ? v : 0.01f * v;  sA = fmaf(v, bw1.y, sA);
                    v = fmaf(acc[mt][nt][2], INV_SCALE, bw0.x);
                    v = (v > 0.f) ? v : 0.01f * v;  sB = fmaf(v, bw0.y, sB);
                    v = fmaf(acc[mt][nt][3], INV_SCALE, bw1.x);
                    v = (v > 0.f) ? v : 0.01f * v;  sB = fmaf(v, bw1.y, sB);
#pragma unroll
                    for (int q = 0; q < 4; ++q) acc[mt][nt][q] = 0.f;
                }
                sA += __shfl_xor_sync(0xffffffffu, sA, 1);
                sA += __shfl_xor_sync(0xffffffffu, sA, 2);
                sB += __shfl_xor_sync(0xffffffffu, sB, 1);
                sB += __shfl_xor_sync(0xffffffffu, sB, 2);
                if ((lane & 3) == 0) {
                    int row = wm * 64 + mt * 16 + (lane >> 2);
                    atomicAdd(&sums[row], sA);
                    atomicAdd(&sums[row + 8], sB);
                }
            }
        }
    }

    __syncthreads();
    if (tid < 128)
        out[(size_t)(mt8 * 128 + tid) * J_DIM + j] = sums[tid] + b1g[j];
}

// ---------------- launch ----------------
extern "C" void kernel_launch(void* const* d_in, const int* in_sizes, int n_in,
                              void* d_out, int out_size) {
    const float* x      = (const float*)d_in[0];
    const int*   ip     = (const int*)d_in[1];
    const float* w      = (const float*)d_in[2];
    const float* W0     = (const float*)d_in[3];
    const float* b0     = (const float*)d_in[4];
    const float* W1     = (const float*)d_in[5];
    const float* b1     = (const float*)d_in[6];
    const float* logvar = (const float*)d_in[7];
    float* out = (float*)d_out;

    const int SMEM_BYTES = 201216;
    cudaFuncSetAttribute(encoder_gemm, cudaFuncAttributeMaxDynamicSharedMemorySize, SMEM_BYTES);

    prep_kernel<<<(J_DIM * H_DIM * K_DIM / 4) / 256, 256>>>(W0, w, ip, x, logvar, out, out_size);
    encoder_gemm<<<J_DIM * (B_DIM / 128), 256, SMEM_BYTES>>>(b0, W1, b1, out);
}

// round 5
// speedup vs baseline: 1.1017x; 1.0146x over previous
#include <cuda_runtime.h>
#include <cuda_fp16.h>
#include <cstdint>

#define B_DIM 1024
#define K_DIM 512
#define H_DIM 512
#define J_DIM 256
#define D_DIM 4

#define SCALE_F 512.0f
#define INV_SCALE (1.0f/512.0f)

// scratch (static device globals: allocation-free)
__device__ __half g_xh[B_DIM * K_DIM];
__device__ __half g_w0h[(size_t)J_DIM * H_DIM * K_DIM];

__device__ __forceinline__ uint32_t smem_u32(const void* p) {
    uint32_t a;
    asm("{ .reg .u64 t; cvta.to.shared.u64 t, %1; cvt.u32.u64 %0, t; }" : "=r"(a) : "l"(p));
    return a;
}

#define CP_ASYNC16(dst, src) \
    asm volatile("cp.async.cg.shared.global [%0], [%1], 16;" \
        :: "r"((uint32_t)(dst)), "l"(src) : "memory")
#define CP_COMMIT() asm volatile("cp.async.commit_group;" ::: "memory")
#define CP_WAIT(n)  asm volatile("cp.async.wait_group %0;" :: "n"(n) : "memory")

#define LDSM_X4(r0,r1,r2,r3,addr) \
    asm volatile("ldmatrix.sync.aligned.m8n8.x4.shared.b16 {%0,%1,%2,%3}, [%4];" \
        : "=r"(r0), "=r"(r1), "=r"(r2), "=r"(r3) : "r"(addr))

#define MMA16816(d, a, b0, b1) \
    asm volatile("mma.sync.aligned.m16n8k16.row.col.f32.f16.f16.f32 " \
        "{%0,%1,%2,%3}, {%4,%5,%6,%7}, {%8,%9}, {%0,%1,%2,%3};" \
        : "+f"((d)[0]), "+f"((d)[1]), "+f"((d)[2]), "+f"((d)[3]) \
        : "r"((a)[0]), "r"((a)[1]), "r"((a)[2]), "r"((a)[3]), "r"(b0), "r"(b1))

// ---------------- merged prep kernel ----------------
__global__ void prep_kernel(const float* __restrict__ W0, const float* __restrict__ w,
                            const int* __restrict__ ip,
                            const float* __restrict__ x, const float* __restrict__ logvar,
                            float* __restrict__ out, int out_size) {
    size_t t = (size_t)blockIdx.x * blockDim.x + threadIdx.x;
    size_t e = t * 4;
    int j = (int)(e >> 18);          // H*K = 2^18
    int k = (int)(e & (K_DIM - 1));
    float4 a = *reinterpret_cast<const float4*>(W0 + e);
    const float* wip = w + (size_t)ip[0] * J_DIM * K_DIM + (size_t)j * K_DIM + k;
    float4 b = *reinterpret_cast<const float4*>(wip);
    __half2 h0 = __floats2half2_rn(a.x * b.x * SCALE_F, a.y * b.y * SCALE_F);
    __half2 h1 = __floats2half2_rn(a.z * b.z * SCALE_F, a.w * b.w * SCALE_F);
    uint2 pk;
    pk.x = *reinterpret_cast<uint32_t*>(&h0);
    pk.y = *reinterpret_cast<uint32_t*>(&h1);
    *reinterpret_cast<uint2*>(g_w0h + e) = pk;

    if (t < (B_DIM * K_DIM) / 4) {
        float4 v = reinterpret_cast<const float4*>(x)[t];
        __half2 x0 = __floats2half2_rn(v.x, v.y);
        __half2 x1 = __floats2half2_rn(v.z, v.w);
        uint2 xp;
        xp.x = *reinterpret_cast<uint32_t*>(&x0);
        xp.y = *reinterpret_cast<uint32_t*>(&x1);
        reinterpret_cast<uint2*>(g_xh)[t] = xp;
    }
    if (blockIdx.x == 0) {
        int extra = out_size - B_DIM * J_DIM;
        if ((int)threadIdx.x < extra && threadIdx.x < D_DIM)
            out[B_DIM * J_DIM + threadIdx.x] = logvar[threadIdx.x];
    }
}

// ---------------- fused grouped-GEMM + epilogue (HMMA, reg-pipelined) ----------------
__global__ void __launch_bounds__(256, 1)
encoder_gemm(const float* __restrict__ b0g, const float* __restrict__ W1g,
             const float* __restrict__ b1g, float* __restrict__ out) {
    extern __shared__ char smem[];
    const uint32_t S_X = smem_u32(smem);            // 131072 B
    const uint32_t S_W = S_X + 131072;              // 2 x 32768 B
    float2* bw   = reinterpret_cast<float2*>(smem + 196608);  // 512 float2
    float*  sums = reinterpret_cast<float*>(smem + 200704);   // 128 floats

    const int tid  = threadIdx.x;
    const int wid  = tid >> 5;
    const int lane = tid & 31;
    const int wm = wid & 1;          // M block (64 rows)
    const int wn = wid >> 1;         // N block (32 cols within 128 h-chunk)
    const int j  = blockIdx.x >> 3;
    const int mt8 = blockIdx.x & 7;

    const __half* Ab = g_xh + (size_t)(mt8 * 128) * K_DIM;
    const __half* Bb = g_w0h + (size_t)j * H_DIM * K_DIM;

    for (int c = tid; c < H_DIM; c += 256)
        bw[c] = make_float2(b0g[j * H_DIM + c], W1g[j * H_DIM + c]);
    if (tid < 128) sums[tid] = 0.f;

    // X tile: 8192 16B chunks, xor-swizzled (64 chunks per 1024B row)
#pragma unroll
    for (int it = 0; it < 32; ++it) {
        int c = tid + it * 256;
        int row = c >> 6, kb = c & 63;
        int swz = (kb & 56) | ((kb ^ row) & 7);
        CP_ASYNC16(S_X + row * 1024 + swz * 16, Ab + (size_t)row * K_DIM + kb * 8);
    }

    // W chunk stage: cc in [0,16): hc = cc>>2, kc = cc&3. 128h x 128k, 256B/row.
    auto stage_w = [&](int cc, int buf) {
        const __half* src = Bb + (size_t)((cc >> 2) * 128) * K_DIM + (cc & 3) * 128;
        uint32_t dstb = S_W + buf * 32768;
#pragma unroll
        for (int it = 0; it < 8; ++it) {
            int c = tid + it * 256;
            int row = c >> 4, kb = c & 15;
            int swz = (kb & 8) | ((kb ^ row) & 7);
            CP_ASYNC16(dstb + row * 256 + swz * 16,
                       src + (size_t)row * K_DIM + kb * 8);
        }
    };

    stage_w(0, 0);
    CP_COMMIT();

    float acc[4][4][4];
#pragma unroll
    for (int mt = 0; mt < 4; ++mt)
#pragma unroll
        for (int nt = 0; nt < 4; ++nt)
#pragma unroll
            for (int q = 0; q < 4; ++q) acc[mt][nt][q] = 0.f;

    // ldmatrix lane-address components (constant per thread)
    const int a_row = wm * 64 + (lane & 15);
    const int a_ck  = lane >> 4;
    const int b_row = wn * 32 + (lane & 7) + ((lane >> 4) << 3);
    const int b_kb  = (lane >> 3) & 1;

    uint32_t afr[2][4][4], bfr[2][2][4];

#pragma unroll 1
    for (int cc = 0; cc < 16; ++cc) {
        int buf = cc & 1;
        CP_WAIT(0);
        __syncthreads();

        uint32_t wbase = S_W + buf * 32768;
        int kc = cc & 3;

        auto fetch = [&](int kk, uint32_t (&af)[4][4], uint32_t (&bf)[2][4]) {
#pragma unroll
            for (int mt = 0; mt < 4; ++mt) {
                int r = a_row + mt * 16;
                int cidx = kc * 16 + kk * 2 + a_ck;
                int swz = (cidx & 56) | ((cidx ^ r) & 7);
                LDSM_X4(af[mt][0], af[mt][1], af[mt][2], af[mt][3],
                        S_X + r * 1024 + swz * 16);
            }
#pragma unroll
            for (int np = 0; np < 2; ++np) {
                int hl = b_row + np * 16;
                int kb = kk * 2 + b_kb;
                int swz = (kb & 8) | ((kb ^ hl) & 7);
                LDSM_X4(bf[np][0], bf[np][1], bf[np][2], bf[np][3],
                        wbase + hl * 256 + swz * 16);
            }
        };

        // prefetch kk=0 fragments BEFORE queueing next stage's cp.asyncs
        fetch(0, afr[0], bfr[0]);
        if (cc < 15) { stage_w(cc + 1, buf ^ 1); CP_COMMIT(); }

#pragma unroll
        for (int kk = 0; kk < 8; ++kk) {
            int cur = kk & 1;
            if (kk < 7) fetch(kk + 1, afr[cur ^ 1], bfr[cur ^ 1]);
#pragma unroll
            for (int mt = 0; mt < 4; ++mt)
#pragma unroll
                for (int nt = 0; nt < 4; ++nt)
                    MMA16816(acc[mt][nt], afr[cur][mt],
                             bfr[cur][nt >> 1][(nt & 1) * 2],
                             bfr[cur][nt >> 1][(nt & 1) * 2 + 1]);
        }

        if (kc == 3) {
            int hc = cc >> 2;
#pragma unroll
            for (int mt = 0; mt < 4; ++mt) {
                float sA = 0.f, sB = 0.f;
#pragma unroll
                for (int nt = 0; nt < 4; ++nt) {
                    int h = hc * 128 + wn * 32 + nt * 8 + (lane & 3) * 2;
                    float2 bw0 = bw[h];
                    float2 bw1 = bw[h + 1];
                    float v;
                    v = fmaf(acc[mt][nt][0], INV_SCALE, bw0.x);
                    v = (v > 0.f) ? v : 0.01f * v;  sA = fmaf(v, bw0.y, sA);
                    v = fmaf(acc[mt][nt][1], INV_SCALE, bw1.x);
                    v = (v > 0.f) ? v : 0.01f * v;  sA = fmaf(v, bw1.y, sA);
                    v = fmaf(acc[mt][nt][2], INV_SCALE, bw0.x);
                    v = (v > 0.f) ? v : 0.01f * v;  sB = fmaf(v, bw0.y, sB);
                    v = fmaf(acc[mt][nt][3], INV_SCALE, bw1.x);
                    v = (v > 0.f) ? v : 0.01f * v;  sB = fmaf(v, bw1.y, sB);
#pragma unroll
                    for (int q = 0; q < 4; ++q) acc[mt][nt][q] = 0.f;
                }
                sA += __shfl_xor_sync(0xffffffffu, sA, 1);
                sA += __shfl_xor_sync(0xffffffffu, sA, 2);
                sB += __shfl_xor_sync(0xffffffffu, sB, 1);
                sB += __shfl_xor_sync(0xffffffffu, sB, 2);
                if ((lane & 3) == 0) {
                    int row = wm * 64 + mt * 16 + (lane >> 2);
                    atomicAdd(&sums[row], sA);
                    atomicAdd(&sums[row + 8], sB);
                }
            }
        }
    }

    __syncthreads();
    if (tid < 128)
        out[(size_t)(mt8 * 128 + tid) * J_DIM + j] = sums[tid] + b1g[j];
}

// ---------------- launch ----------------
extern "C" void kernel_launch(void* const* d_in, const int* in_sizes, int n_in,
                              void* d_out, int out_size) {
    const float* x      = (const float*)d_in[0];
    const int*   ip     = (const int*)d_in[1];
    const float* w      = (const float*)d_in[2];
    const float* W0     = (const float*)d_in[3];
    const float* b0     = (const float*)d_in[4];
    const float* W1     = (const float*)d_in[5];
    const float* b1     = (const float*)d_in[6];
    const float* logvar = (const float*)d_in[7];
    float* out = (float*)d_out;

    const int SMEM_BYTES = 201216;
    cudaFuncSetAttribute(encoder_gemm, cudaFuncAttributeMaxDynamicSharedMemorySize, SMEM_BYTES);

    prep_kernel<<<(J_DIM * H_DIM * K_DIM / 4) / 256, 256>>>(W0, w, ip, x, logvar, out, out_size);
    encoder_gemm<<<J_DIM * (B_DIM / 128), 256, SMEM_BYTES>>>(b0, W1, b1, out);
}

// round 6
// speedup vs baseline: 1.1570x; 1.0502x over previous
#include <cuda_runtime.h>
#include <cuda_fp16.h>
#include <cstdint>

#define B_DIM 1024
#define K_DIM 512
#define H_DIM 512
#define J_DIM 256
#define D_DIM 4

#define SCALE_F 512.0f
#define INV_SCALE (1.0f/512.0f)

// scratch (static device globals: allocation-free)
__device__ __half g_xh[B_DIM * K_DIM];
__device__ __half g_w0h[(size_t)J_DIM * H_DIM * K_DIM];

__device__ __forceinline__ uint32_t smem_u32(const void* p) {
    uint32_t a;
    asm("{ .reg .u64 t; cvta.to.shared.u64 t, %1; cvt.u32.u64 %0, t; }" : "=r"(a) : "l"(p));
    return a;
}

#define CP_ASYNC16(dst, src) \
    asm volatile("cp.async.cg.shared.global [%0], [%1], 16;" \
        :: "r"((uint32_t)(dst)), "l"(src) : "memory")
#define CP_COMMIT() asm volatile("cp.async.commit_group;" ::: "memory")
#define CP_WAIT(n)  asm volatile("cp.async.wait_group %0;" :: "n"(n) : "memory")

#define LDSM_X4(r0,r1,r2,r3,addr) \
    asm volatile("ldmatrix.sync.aligned.m8n8.x4.shared.b16 {%0,%1,%2,%3}, [%4];" \
        : "=r"(r0), "=r"(r1), "=r"(r2), "=r"(r3) : "r"(addr))

#define MMA16816(d, a, b0, b1) \
    asm volatile("mma.sync.aligned.m16n8k16.row.col.f32.f16.f16.f32 " \
        "{%0,%1,%2,%3}, {%4,%5,%6,%7}, {%8,%9}, {%0,%1,%2,%3};" \
        : "+f"((d)[0]), "+f"((d)[1]), "+f"((d)[2]), "+f"((d)[3]) \
        : "r"((a)[0]), "r"((a)[1]), "r"((a)[2]), "r"((a)[3]), "r"(b0), "r"(b1))

// ---------------- merged prep kernel ----------------
__global__ void prep_kernel(const float* __restrict__ W0, const float* __restrict__ w,
                            const int* __restrict__ ip,
                            const float* __restrict__ x, const float* __restrict__ logvar,
                            float* __restrict__ out, int out_size) {
    size_t t = (size_t)blockIdx.x * blockDim.x + threadIdx.x;
    size_t e = t * 4;
    int j = (int)(e >> 18);          // H*K = 2^18
    int k = (int)(e & (K_DIM - 1));
    float4 a = *reinterpret_cast<const float4*>(W0 + e);
    const float* wip = w + (size_t)ip[0] * J_DIM * K_DIM + (size_t)j * K_DIM + k;
    float4 b = *reinterpret_cast<const float4*>(wip);
    __half2 h0 = __floats2half2_rn(a.x * b.x * SCALE_F, a.y * b.y * SCALE_F);
    __half2 h1 = __floats2half2_rn(a.z * b.z * SCALE_F, a.w * b.w * SCALE_F);
    uint2 pk;
    pk.x = *reinterpret_cast<uint32_t*>(&h0);
    pk.y = *reinterpret_cast<uint32_t*>(&h1);
    *reinterpret_cast<uint2*>(g_w0h + e) = pk;

    if (t < (B_DIM * K_DIM) / 4) {
        float4 v = reinterpret_cast<const float4*>(x)[t];
        __half2 x0 = __floats2half2_rn(v.x, v.y);
        __half2 x1 = __floats2half2_rn(v.z, v.w);
        uint2 xp;
        xp.x = *reinterpret_cast<uint32_t*>(&x0);
        xp.y = *reinterpret_cast<uint32_t*>(&x1);
        reinterpret_cast<uint2*>(g_xh)[t] = xp;
    }
    if (blockIdx.x == 0) {
        int extra = out_size - B_DIM * J_DIM;
        if ((int)threadIdx.x < extra && threadIdx.x < D_DIM)
            out[B_DIM * J_DIM + threadIdx.x] = logvar[threadIdx.x];
    }
}

// ---------------- fused grouped-GEMM + overlapped epilogue ----------------
__global__ void __launch_bounds__(256, 1)
encoder_gemm(const float* __restrict__ b0g, const float* __restrict__ W1g,
             const float* __restrict__ b1g, float* __restrict__ out) {
    extern __shared__ char smem[];
    const uint32_t S_X = smem_u32(smem);            // 131072 B
    const uint32_t S_W = S_X + 131072;              // 2 x 32768 B
    float2* bw   = reinterpret_cast<float2*>(smem + 196608);  // 512 float2
    float*  sums = reinterpret_cast<float*>(smem + 200704);   // 128 floats

    const int tid  = threadIdx.x;
    const int wid  = tid >> 5;
    const int lane = tid & 31;
    const int wm = wid & 1;          // M block (64 rows)
    const int wn = wid >> 1;         // N block (32 cols within 128 h-chunk)
    const int j  = blockIdx.x >> 3;
    const int mt8 = blockIdx.x & 7;

    const __half* Ab = g_xh + (size_t)(mt8 * 128) * K_DIM;
    const __half* Bb = g_w0h + (size_t)j * H_DIM * K_DIM;

    for (int c = tid; c < H_DIM; c += 256)
        bw[c] = make_float2(b0g[j * H_DIM + c], W1g[j * H_DIM + c]);
    if (tid < 128) sums[tid] = 0.f;

    // X tile: 8192 16B chunks, xor-swizzled (64 chunks per 1024B row)
#pragma unroll
    for (int it = 0; it < 32; ++it) {
        int c = tid + it * 256;
        int row = c >> 6, kb = c & 63;
        int swz = (kb & 56) | ((kb ^ row) & 7);
        CP_ASYNC16(S_X + row * 1024 + swz * 16, Ab + (size_t)row * K_DIM + kb * 8);
    }

    // W chunk stage: cc in [0,16): hc = cc>>2, kc = cc&3. 128h x 128k, 256B/row.
    auto stage_w = [&](int cc, int buf) {
        const __half* src = Bb + (size_t)((cc >> 2) * 128) * K_DIM + (cc & 3) * 128;
        uint32_t dstb = S_W + buf * 32768;
#pragma unroll
        for (int it = 0; it < 8; ++it) {
            int c = tid + it * 256;
            int row = c >> 4, kb = c & 15;
            int swz = (kb & 8) | ((kb ^ row) & 7);
            CP_ASYNC16(dstb + row * 256 + swz * 16,
                       src + (size_t)row * K_DIM + kb * 8);
        }
    };

    stage_w(0, 0);
    CP_COMMIT();

    float acc[4][4][4];
#pragma unroll
    for (int mt = 0; mt < 4; ++mt)
#pragma unroll
        for (int nt = 0; nt < 4; ++nt)
#pragma unroll
            for (int q = 0; q < 4; ++q) acc[mt][nt][q] = 0.f;

    uint32_t stash[4][4][2];   // prev h-chunk acc, packed fp16
    float mu[4][2];            // per-mt partial output dots
#pragma unroll
    for (int mt = 0; mt < 4; ++mt) { mu[mt][0] = 0.f; mu[mt][1] = 0.f; }

    const int a_row = wm * 64 + (lane & 15);
    const int a_ck  = lane >> 4;
    const int b_row = wn * 32 + (lane & 7) + ((lane >> 4) << 3);
    const int b_kb  = (lane >> 3) & 1;
    const int h_off = wn * 32 + (lane & 3) * 2;

    uint32_t afr[2][4][4], bfr[2][2][4];

    auto fetchA = [&](int kcL, int kk, uint32_t (&af)[4][4]) {
#pragma unroll
        for (int mt = 0; mt < 4; ++mt) {
            int r = a_row + mt * 16;
            int cidx = kcL * 16 + kk * 2 + a_ck;
            int swz = (cidx & 56) | ((cidx ^ r) & 7);
            LDSM_X4(af[mt][0], af[mt][1], af[mt][2], af[mt][3],
                    S_X + r * 1024 + swz * 16);
        }
    };
    auto fetchB = [&](uint32_t wbase, int kk, uint32_t (&bf)[2][4]) {
#pragma unroll
        for (int np = 0; np < 2; ++np) {
            int hl = b_row + np * 16;
            int kb = kk * 2 + b_kb;
            int swz = (kb & 8) | ((kb ^ hl) & 7);
            LDSM_X4(bf[np][0], bf[np][1], bf[np][2], bf[np][3],
                    wbase + hl * 256 + swz * 16);
        }
    };
    // one mt-slice of the deferred epilogue (reads fp16 stash, updates mu)
    auto epi_slice = [&](int mt, int hbase) {
        float sA = mu[mt][0], sB = mu[mt][1];
#pragma unroll
        for (int nt = 0; nt < 4; ++nt) {
            int h = hbase + h_off + nt * 8;
            float2 bw0 = bw[h];
            float2 bw1 = bw[h + 1];
            __half2 hp0 = *reinterpret_cast<__half2*>(&stash[mt][nt][0]);
            __half2 hp1 = *reinterpret_cast<__half2*>(&stash[mt][nt][1]);
            float2 p0 = __half22float2(hp0);
            float2 p1 = __half22float2(hp1);
            float v;
            v = fmaf(p0.x, INV_SCALE, bw0.x); v = (v > 0.f) ? v : 0.01f * v; sA = fmaf(v, bw0.y, sA);
            v = fmaf(p0.y, INV_SCALE, bw1.x); v = (v > 0.f) ? v : 0.01f * v; sA = fmaf(v, bw1.y, sA);
            v = fmaf(p1.x, INV_SCALE, bw0.x); v = (v > 0.f) ? v : 0.01f * v; sB = fmaf(v, bw0.y, sB);
            v = fmaf(p1.y, INV_SCALE, bw1.x); v = (v > 0.f) ? v : 0.01f * v; sB = fmaf(v, bw1.y, sB);
        }
        mu[mt][0] = sA; mu[mt][1] = sB;
    };

#pragma unroll 1
    for (int cc = 0; cc < 16; ++cc) {
        int buf = cc & 1;
        CP_WAIT(0);
        __syncthreads();

        uint32_t wbase = S_W + buf * 32768;
        int kc = cc & 3;
        const bool do_epi = (kc == 0) && (cc > 0);
        const int hbase = ((cc >> 2) - 1) * 128;   // only used when do_epi

        if (cc == 0) fetchA(0, 0, afr[0]);   // cold start; otherwise prefetched
        fetchB(wbase, 0, bfr[0]);
        if (cc < 15) { stage_w(cc + 1, buf ^ 1); CP_COMMIT(); }

#pragma unroll
        for (int kk = 0; kk < 8; ++kk) {
            int cur = kk & 1;
            if (kk < 7) {
                fetchA(kc, kk + 1, afr[cur ^ 1]);
                fetchB(wbase, kk + 1, bfr[cur ^ 1]);
            } else if (cc < 15) {
                // cross-barrier A prefetch (X tile is immutable)
                fetchA((cc + 1) & 3, 0, afr[0]);
            }
#pragma unroll
            for (int mt = 0; mt < 4; ++mt)
#pragma unroll
                for (int nt = 0; nt < 4; ++nt)
                    MMA16816(acc[mt][nt], afr[cur][mt],
                             bfr[cur][nt >> 1][(nt & 1) * 2],
                             bfr[cur][nt >> 1][(nt & 1) * 2 + 1]);
            if (do_epi && (kk & 1)) epi_slice(kk >> 1, hbase);
        }

        if (kc == 3) {
            // stash finished h-chunk in fp16, clear acc for next chunk
#pragma unroll
            for (int mt = 0; mt < 4; ++mt)
#pragma unroll
                for (int nt = 0; nt < 4; ++nt) {
                    __half2 hp0 = __floats2half2_rn(acc[mt][nt][0], acc[mt][nt][1]);
                    __half2 hp1 = __floats2half2_rn(acc[mt][nt][2], acc[mt][nt][3]);
                    stash[mt][nt][0] = *reinterpret_cast<uint32_t*>(&hp0);
                    stash[mt][nt][1] = *reinterpret_cast<uint32_t*>(&hp1);
                    acc[mt][nt][0] = 0.f; acc[mt][nt][1] = 0.f;
                    acc[mt][nt][2] = 0.f; acc[mt][nt][3] = 0.f;
                }
        }
    }

    // epilogue for last h-chunk (hc=3) + final reduction
#pragma unroll
    for (int mt = 0; mt < 4; ++mt) {
        epi_slice(mt, 3 * 128);
        float sA = mu[mt][0], sB = mu[mt][1];
        sA += __shfl_xor_sync(0xffffffffu, sA, 1);
        sA += __shfl_xor_sync(0xffffffffu, sA, 2);
        sB += __shfl_xor_sync(0xffffffffu, sB, 1);
        sB += __shfl_xor_sync(0xffffffffu, sB, 2);
        if ((lane & 3) == 0) {
            int row = wm * 64 + mt * 16 + (lane >> 2);
            atomicAdd(&sums[row], sA);
            atomicAdd(&sums[row + 8], sB);
        }
    }

    __syncthreads();
    if (tid < 128)
        out[(size_t)(mt8 * 128 + tid) * J_DIM + j] = sums[tid] + b1g[j];
}

// ---------------- launch ----------------
extern "C" void kernel_launch(void* const* d_in, const int* in_sizes, int n_in,
                              void* d_out, int out_size) {
    const float* x      = (const float*)d_in[0];
    const int*   ip     = (const int*)d_in[1];
    const float* w      = (const float*)d_in[2];
    const float* W0     = (const float*)d_in[3];
    const float* b0     = (const float*)d_in[4];
    const float* W1     = (const float*)d_in[5];
    const float* b1     = (const float*)d_in[6];
    const float* logvar = (const float*)d_in[7];
    float* out = (float*)d_out;

    const int SMEM_BYTES = 201216;
    cudaFuncSetAttribute(encoder_gemm, cudaFuncAttributeMaxDynamicSharedMemorySize, SMEM_BYTES);

    prep_kernel<<<(J_DIM * H_DIM * K_DIM / 4) / 256, 256>>>(W0, w, ip, x, logvar, out, out_size);
    encoder_gemm<<<J_DIM * (B_DIM / 128), 256, SMEM_BYTES>>>(b0, W1, b1, out);
}